// round 3
// baseline (speedup 1.0000x reference)
#include <cuda_runtime.h>
#include <math.h>

#define BATCH        2048
#define IN_DIM       4096
#define OUT_DIM      1024
#define N_EDGES_MAX  16384
#define ROWS_PER_BLK 4
#define THREADS      1024   // == OUT_DIM, one node per thread

// CSR offsets + packed edges (src, weight-as-int). __device__ scratch (no allocs).
__device__ int  g_offs[OUT_DIM + 1];
__device__ int2 g_edges[N_EDGES_MAX];

// Prologue: pack edges, and build offs[o] = lower_bound(edge_dst, o).
__global__ void prologue_kernel(const int* __restrict__ edge_src,
                                const float* __restrict__ weights,
                                const int* __restrict__ edge_dst,
                                int n_edges) {
    int i = blockIdx.x * blockDim.x + threadIdx.x;
    if (i < n_edges)
        g_edges[i] = make_int2(edge_src[i], __float_as_int(weights[i]));
    if (i <= OUT_DIM) {
        int lo = 0, hi = n_edges;
        while (lo < hi) {
            int mid = (lo + hi) >> 1;
            if (edge_dst[mid] < i) lo = mid + 1; else hi = mid;
        }
        g_offs[i] = lo;
    }
}

// Main kernel: 4 batch rows per block, transposed smem tile xs_t[IN_DIM] of
// float4 (one column's 4 row-values contiguous => 1 LDS.128 per edge).
extern __shared__ float4 xs_t[];  // [IN_DIM] float4 = 64 KB

__device__ __forceinline__ float4 fma4(float4 v, float w, float4 a) {
    a.x = fmaf(v.x, w, a.x);
    a.y = fmaf(v.y, w, a.y);
    a.z = fmaf(v.z, w, a.z);
    a.w = fmaf(v.w, w, a.w);
    return a;
}

__global__ __launch_bounds__(THREADS, 2)
void sparse_node_main_kernel(const float* __restrict__ x,
                             float* __restrict__ out) {
    const int r0 = blockIdx.x * ROWS_PER_BLK;
    const int t  = threadIdx.x;

    // ---- Stage: thread t owns columns 4t..4t+3. Load one float4 per row
    // (coalesced LDG.128), transpose in registers, store 4 column-float4s
    // with rotated issue order to spread banks. ----
    {
        const float4* __restrict__ xg = reinterpret_cast<const float4*>(x);
        const int row_q = IN_DIM / 4;  // float4s per row
        float4 a0 = xg[(size_t)(r0 + 0) * row_q + t];
        float4 a1 = xg[(size_t)(r0 + 1) * row_q + t];
        float4 a2 = xg[(size_t)(r0 + 2) * row_q + t];
        float4 a3 = xg[(size_t)(r0 + 3) * row_q + t];
        float4 c[4];
        c[0] = make_float4(a0.x, a1.x, a2.x, a3.x);
        c[1] = make_float4(a0.y, a1.y, a2.y, a3.y);
        c[2] = make_float4(a0.z, a1.z, a2.z, a3.z);
        c[3] = make_float4(a0.w, a1.w, a2.w, a3.w);
        #pragma unroll
        for (int i = 0; i < 4; i++) {
            int j = (i + t) & 3;             // rotate issue order per lane
            xs_t[4 * t + j] = c[j];
        }
    }
    __syncthreads();

    // ---- Node-centric edge walk: thread t owns output node t ----
    const int beg = g_offs[t];
    const int end = g_offs[t + 1];

    float4 acc = make_float4(0.f, 0.f, 0.f, 0.f);
    int e = beg;
    for (; e + 1 < end; e += 2) {
        int2 p0 = __ldg(&g_edges[e]);
        int2 p1 = __ldg(&g_edges[e + 1]);
        float4 v0 = xs_t[p0.x];
        float4 v1 = xs_t[p1.x];
        acc = fma4(v0, __int_as_float(p0.y), acc);
        acc = fma4(v1, __int_as_float(p1.y), acc);
    }
    if (e < end) {
        int2 p = __ldg(&g_edges[e]);
        acc = fma4(xs_t[p.x], __int_as_float(p.y), acc);
    }

    // ---- Fused tanh -> sigmoid, coalesced stores ----
    float h, s;
    h = tanhf(acc.x); s = 1.f / (1.f + __expf(-h));
    out[(size_t)(r0 + 0) * OUT_DIM + t] = s;
    h = tanhf(acc.y); s = 1.f / (1.f + __expf(-h));
    out[(size_t)(r0 + 1) * OUT_DIM + t] = s;
    h = tanhf(acc.z); s = 1.f / (1.f + __expf(-h));
    out[(size_t)(r0 + 2) * OUT_DIM + t] = s;
    h = tanhf(acc.w); s = 1.f / (1.f + __expf(-h));
    out[(size_t)(r0 + 3) * OUT_DIM + t] = s;
}

extern "C" void kernel_launch(void* const* d_in, const int* in_sizes, int n_in,
                              void* d_out, int out_size) {
    const float* x        = (const float*)d_in[0];   // [2048, 4096] f32
    const float* weights  = (const float*)d_in[1];   // [16384] f32
    const int*   edge_src = (const int*)d_in[2];     // [16384] i32
    const int*   edge_dst = (const int*)d_in[3];     // [16384] i32 (sorted)
    float*       out      = (float*)d_out;           // [2048, 1024] f32

    const int n_edges = in_sizes[1];

    static bool attr_set = false;
    if (!attr_set) {
        cudaFuncSetAttribute(sparse_node_main_kernel,
                             cudaFuncAttributeMaxDynamicSharedMemorySize,
                             IN_DIM * (int)sizeof(float4));  // 64 KB
        attr_set = true;
    }

    // 1) Pack edges + CSR offsets (single tiny launch)
    int pro_threads = (n_edges > OUT_DIM + 1 ? n_edges : OUT_DIM + 1);
    prologue_kernel<<<(pro_threads + 127) / 128, 128>>>(edge_src, weights,
                                                        edge_dst, n_edges);

    // 2) Main fused kernel: 512 blocks x 1024 threads, 64 KB smem (2 blocks/SM)
    const int grid = BATCH / ROWS_PER_BLK;  // 512
    sparse_node_main_kernel<<<grid, THREADS, IN_DIM * sizeof(float4)>>>(x, out);
}